// round 9
// baseline (speedup 1.0000x reference)
#include <cuda_runtime.h>
#include <cuda_fp16.h>
#include <cstdint>
#include <math.h>

// ---------------------------------------------------------------------------
// Luong 'general' attention, B=16, T=S=E=D=1024.
// Out: [h_tilde | attn_weights | attn_energies] fp32.
// Stages 1,2: fp16 3-term split mma (softmax-safe).  Stage 4: fp16 2-term.
// Stage 5: int8 2-digit fixed-point mma.m16n8k32.s8 (2x rate), tanh epilogue.
// ---------------------------------------------------------------------------

typedef __half hf;

#define BATCH 16
#define TDIM 1024
#define SDIM 1024
#define EDIM 1024
#define DDIM 1024
#define NBT (16 * 1024 * 1024)

// quantization scales for stage 5
#define QSA (16384.0f / 6.5f)     // ctx / hidden (|x| < ~5.8)
#define QSB (16384.0f / 0.125f)   // W_out (|x| < ~0.11)

__device__ __align__(256) hf g_enc_h[NBT],  g_enc_l[NBT];
__device__ __align__(256) hf g_encT_h[NBT], g_encT_l[NBT];
__device__ __align__(256) hf g_hid_h[NBT],  g_hid_l[NBT];
__device__ __align__(256) hf g_proj_h[NBT], g_proj_l[NBT];
__device__ __align__(256) hf g_wts_h[NBT],  g_wts_l[NBT];
__device__ __align__(256) hf g_wa_h[1024 * 1024], g_wa_l[1024 * 1024];
__device__ __align__(256) char g_ctx_q1[NBT], g_ctx_q2[NBT];   // ctx s8 digits
__device__ __align__(256) char g_hid_q1[NBT], g_hid_q2[NBT];   // hidden s8 digits
__device__ __align__(256) char g_wo_q1[1024 * 2048], g_wo_q2[1024 * 2048];

// ------------------------------ PTX helpers --------------------------------
__device__ __forceinline__ uint32_t smem_u32(const void* p) {
    uint32_t a;
    asm("{ .reg .u64 t; cvta.to.shared.u64 t, %1; cvt.u32.u64 %0, t; }"
        : "=r"(a) : "l"(p));
    return a;
}
__device__ __forceinline__ uint32_t swz(uint32_t off)   { return off ^ ((off >> 3) & 0x70); } // SW128
__device__ __forceinline__ uint32_t swz64(uint32_t off) { return off ^ ((off >> 3) & 0x30); } // SW64

#define CP_ASYNC16(saddr, gptr) \
    asm volatile("cp.async.cg.shared.global [%0], [%1], 16;" \
                 :: "r"(saddr), "l"(gptr) : "memory")
#define CP_COMMIT() asm volatile("cp.async.commit_group;" ::: "memory")
#define CP_WAITN(n) asm volatile("cp.async.wait_group %0;" :: "n"(n) : "memory")

#define LDSM4(r0, r1, r2, r3, addr) \
    asm volatile("ldmatrix.sync.aligned.m8n8.x4.shared.b16 {%0,%1,%2,%3}, [%4];" \
                 : "=r"(r0), "=r"(r1), "=r"(r2), "=r"(r3) : "r"(addr))

#define MMA16816(d, a, b0, b1) \
    asm volatile("mma.sync.aligned.m16n8k16.row.col.f32.f16.f16.f32 " \
                 "{%0,%1,%2,%3}, {%4,%5,%6,%7}, {%8,%9}, {%0,%1,%2,%3};" \
                 : "+f"((d)[0]), "+f"((d)[1]), "+f"((d)[2]), "+f"((d)[3]) \
                 : "r"((a)[0]), "r"((a)[1]), "r"((a)[2]), "r"((a)[3]), \
                   "r"(b0), "r"(b1))

#define IMMA16832(d, a, b0, b1) \
    asm volatile("mma.sync.aligned.m16n8k32.row.col.s32.s8.s8.s32 " \
                 "{%0,%1,%2,%3}, {%4,%5,%6,%7}, {%8,%9}, {%0,%1,%2,%3};" \
                 : "+r"((d)[0]), "+r"((d)[1]), "+r"((d)[2]), "+r"((d)[3]) \
                 : "r"((a)[0]), "r"((a)[1]), "r"((a)[2]), "r"((a)[3]), \
                   "r"(b0), "r"(b1))

__device__ __forceinline__ uint32_t packh(hf a, hf b) {
    __half2 t; t.x = a; t.y = b;
    return *reinterpret_cast<uint32_t*>(&t);
}
__device__ __forceinline__ void quant2(float x, float scale, int& d1, int& d2) {
    float xs = x * scale;
    xs = fminf(fmaxf(xs, -16250.0f), 16250.0f);
    float r1 = rintf(xs * (1.0f / 128.0f));
    d1 = (int)r1;
    d2 = (int)rintf(xs - 128.0f * r1);
}

// =========================== fp16 GEMM (stages 1,2,4) =======================
// Buffer (64KB): [Ah 16K][Al 16K][Bh 16K][Bl 16K], 3-stage pipeline = 192KB.
#define BUF_BYTES 65536
#define SMEM_BYTES (3 * BUF_BYTES)

template<int NT>
__device__ __forceinline__ void stage_loads(
    uint32_t sbuf, const hf* pah, const hf* pal, const hf* pbh, const hf* pbl,
    int bm, int bn, int ldA, int ldB, int k0, int tid)
{
    #pragma unroll
    for (int j = 0; j < 4; ++j) {
        const int idx = tid + j * 256;
        const int r = idx >> 3, g = idx & 7;
        const uint32_t so = swz((uint32_t)(r * 128 + g * 16));
        const size_t ao = (size_t)(bm + r) * ldA + k0 + g * 8;
        const size_t bo = (size_t)(bn + r) * ldB + k0 + g * 8;
        CP_ASYNC16(sbuf + so, pah + ao);
        if (NT == 3) CP_ASYNC16(sbuf + 16384 + so, pal + ao);
        CP_ASYNC16(sbuf + 32768 + so, pbh + bo);
        CP_ASYNC16(sbuf + 49152 + so, pbl + bo);
    }
}

// EPI: 0 = f32 store, 1 = bias + fp16 split, 4 = s8 2-digit quant store
template<int EPI, int NT>
__global__ void __launch_bounds__(256, 1)
mma_gemm(const hf* __restrict__ Ah, const hf* __restrict__ Al,
         const hf* __restrict__ Bh, const hf* __restrict__ Bl,
         const float* __restrict__ bias,
         float* __restrict__ Cf, hf* __restrict__ Ch, hf* __restrict__ Cl,
         int NC, int lda, int ldb, int ldc,
         long long sA, long long sB, long long sC)
{
    extern __shared__ char smem[];
    const uint32_t sb = smem_u32(smem);
    const int tid  = threadIdx.x;
    const int wid  = tid >> 5;
    const int lane = tid & 31;
    const long long z = blockIdx.z;
    Ah += z * sA; Al += z * sA; Bh += z * sB; Bl += z * sB;
    float* cf = Cf;
    char *cq1 = nullptr, *cq2 = nullptr;
    if (EPI == 0) cf += z * sC;
    else if (EPI == 1) { Ch += z * sC; Cl += z * sC; }
    else { cq1 = ((char*)Ch) + z * sC; cq2 = ((char*)Cl) + z * sC; }

    const int bm = blockIdx.y * 128;
    const int bn = blockIdx.x * 128;
    const int wm = (wid >> 2) * 64;
    const int wn = (wid & 3) * 32;

    float acc[4][4][4];
    #pragma unroll
    for (int i = 0; i < 4; i++)
        #pragma unroll
        for (int j = 0; j < 4; j++)
            #pragma unroll
            for (int q = 0; q < 4; q++) acc[i][j][q] = 0.0f;

    stage_loads<NT>(sb, Ah, Al, Bh, Bl, bm, bn, lda, ldb, 0, tid);
    CP_COMMIT();
    if (NC > 1) stage_loads<NT>(sb + BUF_BYTES, Ah, Al, Bh, Bl, bm, bn, lda, ldb, 64, tid);
    CP_COMMIT();

    for (int c = 0; c < NC; ++c) {
        CP_WAITN(1);
        __syncthreads();

        if (c + 2 < NC) {
            const int cn = c + 2;
            stage_loads<NT>(sb + (uint32_t)(cn % 3) * BUF_BYTES,
                            Ah, Al, Bh, Bl, bm, bn, lda, ldb, cn * 64, tid);
            CP_COMMIT();
        }

        const uint32_t ab = sb + (uint32_t)(c % 3) * BUF_BYTES;
        const uint32_t bb = ab + 32768;

        #pragma unroll
        for (int ks = 0; ks < 4; ++ks) {
            uint32_t ah[4][4], al[4][4], bh[2][4], bl[2][4];
            const int arow = wm + (lane & 15);
            const int akb  = ks * 32 + ((lane >> 4) << 4);
            #pragma unroll
            for (int mi = 0; mi < 4; ++mi) {
                const uint32_t ad = ab + swz((uint32_t)((arow + mi * 16) * 128 + akb));
                LDSM4(ah[mi][0], ah[mi][1], ah[mi][2], ah[mi][3], ad);
                if (NT == 3) LDSM4(al[mi][0], al[mi][1], al[mi][2], al[mi][3], ad + 16384);
            }
            const int brow = wn + (lane & 7) + ((lane >> 4) << 3);
            const int bkb  = ks * 32 + (((lane >> 3) & 1) << 4);
            #pragma unroll
            for (int nj = 0; nj < 2; ++nj) {
                const uint32_t bd = bb + swz((uint32_t)((brow + nj * 16) * 128 + bkb));
                LDSM4(bh[nj][0], bh[nj][1], bh[nj][2], bh[nj][3], bd);
                LDSM4(bl[nj][0], bl[nj][1], bl[nj][2], bl[nj][3], bd + 16384);
            }
            #pragma unroll
            for (int mi = 0; mi < 4; ++mi)
                #pragma unroll
                for (int o = 0; o < 4; ++o) {
                    const uint32_t b0h = bh[o >> 1][(o & 1) * 2];
                    const uint32_t b1h = bh[o >> 1][(o & 1) * 2 + 1];
                    const uint32_t b0l = bl[o >> 1][(o & 1) * 2];
                    const uint32_t b1l = bl[o >> 1][(o & 1) * 2 + 1];
                    MMA16816(acc[mi][o], ah[mi], b0h, b1h);
                    MMA16816(acc[mi][o], ah[mi], b0l, b1l);
                    if (NT == 3) MMA16816(acc[mi][o], al[mi], b0h, b1h);
                }
        }
    }

    // ------------------------------- epilogue ------------------------------
    const int rbase = bm + wm + (lane >> 2);
    const int cbase = bn + wn + (lane & 3) * 2;
    #pragma unroll
    for (int mi = 0; mi < 4; ++mi) {
        #pragma unroll
        for (int o = 0; o < 4; ++o) {
            const long long r0 = rbase + mi * 16;
            const int col = cbase + o * 8;
            float c0 = acc[mi][o][0], c1 = acc[mi][o][1];
            float c2 = acc[mi][o][2], c3 = acc[mi][o][3];
            if (EPI == 1) {
                const float bv0 = __ldg(bias + col), bv1 = __ldg(bias + col + 1);
                c0 += bv0; c1 += bv1; c2 += bv0; c3 += bv1;
            }
            if (EPI == 0) {
                *(float2*)(cf + r0 * ldc + col)       = make_float2(c0, c1);
                *(float2*)(cf + (r0 + 8) * ldc + col) = make_float2(c2, c3);
            } else if (EPI == 1) {
                hf h0 = __float2half_rn(c0), h1 = __float2half_rn(c1);
                hf h2 = __float2half_rn(c2), h3 = __float2half_rn(c3);
                hf l0 = __float2half_rn(c0 - __half2float(h0));
                hf l1 = __float2half_rn(c1 - __half2float(h1));
                hf l2 = __float2half_rn(c2 - __half2float(h2));
                hf l3 = __float2half_rn(c3 - __half2float(h3));
                *(uint32_t*)(Ch + r0 * ldc + col)       = packh(h0, h1);
                *(uint32_t*)(Ch + (r0 + 8) * ldc + col) = packh(h2, h3);
                *(uint32_t*)(Cl + r0 * ldc + col)       = packh(l0, l1);
                *(uint32_t*)(Cl + (r0 + 8) * ldc + col) = packh(l2, l3);
            } else {   // EPI == 4: s8 2-digit quantized store (scale QSA)
                int d10, d20, d11, d21, d12, d22, d13, d23;
                quant2(c0, QSA, d10, d20); quant2(c1, QSA, d11, d21);
                quant2(c2, QSA, d12, d22); quant2(c3, QSA, d13, d23);
                char2 p;
                p.x = (char)d10; p.y = (char)d11; *(char2*)(cq1 + r0 * ldc + col) = p;
                p.x = (char)d20; p.y = (char)d21; *(char2*)(cq2 + r0 * ldc + col) = p;
                p.x = (char)d12; p.y = (char)d13; *(char2*)(cq1 + (r0 + 8) * ldc + col) = p;
                p.x = (char)d22; p.y = (char)d23; *(char2*)(cq2 + (r0 + 8) * ldc + col) = p;
            }
        }
    }
}

// =========================== int8 GEMM (stage 5) ============================
// K-chunk 64 s8 (64B rows, SW64). Buffer 32KB: [A1 8K][A2 8K][B1 8K][B2 8K].
#define QBUF_BYTES 32768
#define QSMEM_BYTES (3 * QBUF_BYTES)

__device__ __forceinline__ void stage_loads_q(
    uint32_t sbuf, const char* pa1, const char* pa2, const char* pb1, const char* pb2,
    int bm, int bn, int ldA, int ldB, int k0, int tid)
{
    #pragma unroll
    for (int j = 0; j < 2; ++j) {
        const int idx = tid + j * 256;            // 0..511
        const int r = idx >> 2, g = idx & 3;      // 128 rows x 4 x 16B
        const uint32_t so = swz64((uint32_t)(r * 64 + g * 16));
        const size_t ao = (size_t)(bm + r) * ldA + k0 + g * 16;
        const size_t bo = (size_t)(bn + r) * ldB + k0 + g * 16;
        CP_ASYNC16(sbuf + so,         pa1 + ao);
        CP_ASYNC16(sbuf + 8192 + so,  pa2 + ao);
        CP_ASYNC16(sbuf + 16384 + so, pb1 + bo);
        CP_ASYNC16(sbuf + 24576 + so, pb2 + bo);
    }
}

// h_tilde = tanh( (A1 @ B1^T + A2 @ B2^T) / (QSA*QSB) ), 2-digit s8 operands.
__global__ void __launch_bounds__(256, 1)
imma_tanh(const char* __restrict__ Aq1, const char* __restrict__ Aq2,
          const char* __restrict__ Bq1, const char* __restrict__ Bq2,
          const char* __restrict__ A2q1, const char* __restrict__ A2q2,
          const char* __restrict__ B2q1, const char* __restrict__ B2q2,
          float* __restrict__ Cf,
          int NC1, int NC2, int lda, int ldb, int lda2, int ldb2, int ldc)
{
    extern __shared__ char smem[];
    const uint32_t sb = smem_u32(smem);
    const int tid  = threadIdx.x;
    const int wid  = tid >> 5;
    const int lane = tid & 31;

    const int bm = blockIdx.y * 128;
    const int bn = blockIdx.x * 128;
    const int wm = (wid >> 2) * 64;
    const int wn = (wid & 3) * 32;

    int accH[4][4][4], accL[4][4][4];
    #pragma unroll
    for (int i = 0; i < 4; i++)
        #pragma unroll
        for (int j = 0; j < 4; j++)
            #pragma unroll
            for (int q = 0; q < 4; q++) { accH[i][j][q] = 0; accL[i][j][q] = 0; }

    const int NC = NC1 + NC2;

    stage_loads_q(sb, Aq1, Aq2, Bq1, Bq2, bm, bn, lda, ldb, 0, tid);
    CP_COMMIT();
    if (NC > 1) {
        if (1 < NC1) stage_loads_q(sb + QBUF_BYTES, Aq1, Aq2, Bq1, Bq2, bm, bn, lda, ldb, 64, tid);
        else         stage_loads_q(sb + QBUF_BYTES, A2q1, A2q2, B2q1, B2q2, bm, bn, lda2, ldb2, 0, tid);
    }
    CP_COMMIT();

    for (int c = 0; c < NC; ++c) {
        CP_WAITN(1);
        __syncthreads();

        if (c + 2 < NC) {
            const int cn = c + 2;
            const uint32_t nb = sb + (uint32_t)(cn % 3) * QBUF_BYTES;
            if (cn < NC1)
                stage_loads_q(nb, Aq1, Aq2, Bq1, Bq2, bm, bn, lda, ldb, cn * 64, tid);
            else
                stage_loads_q(nb, A2q1, A2q2, B2q1, B2q2, bm, bn, lda2, ldb2, (cn - NC1) * 64, tid);
            CP_COMMIT();
        }

        const uint32_t ab = sb + (uint32_t)(c % 3) * QBUF_BYTES;
        const uint32_t bb = ab + 16384;

        #pragma unroll
        for (int ks = 0; ks < 2; ++ks) {           // k32 s8 = 32B per step
            uint32_t b1[2][4], b2[2][4];
            const int brow = wn + (lane & 7) + ((lane >> 4) << 3);
            const int bkb  = ks * 32 + (((lane >> 3) & 1) << 4);
            #pragma unroll
            for (int nj = 0; nj < 2; ++nj) {
                const uint32_t bd = bb + swz64((uint32_t)((brow + nj * 16) * 64 + bkb));
                LDSM4(b1[nj][0], b1[nj][1], b1[nj][2], b1[nj][3], bd);
                LDSM4(b2[nj][0], b2[nj][1], b2[nj][2], b2[nj][3], bd + 8192);
            }
            const int arow = wm + (lane & 15);
            const int akb  = ks * 32 + ((lane >> 4) << 4);
            #pragma unroll
            for (int mi = 0; mi < 4; ++mi) {
                uint32_t a1[4], a2[4];
                const uint32_t ad = ab + swz64((uint32_t)((arow + mi * 16) * 64 + akb));
                LDSM4(a1[0], a1[1], a1[2], a1[3], ad);
                LDSM4(a2[0], a2[1], a2[2], a2[3], ad + 8192);
                #pragma unroll
                for (int o = 0; o < 4; ++o) {
                    const uint32_t p0 = b1[o >> 1][(o & 1) * 2];
                    const uint32_t p1 = b1[o >> 1][(o & 1) * 2 + 1];
                    const uint32_t q0 = b2[o >> 1][(o & 1) * 2];
                    const uint32_t q1 = b2[o >> 1][(o & 1) * 2 + 1];
                    IMMA16832(accH[mi][o], a1, p0, p1);   // d1*e1
                    IMMA16832(accL[mi][o], a1, q0, q1);   // d1*e2
                    IMMA16832(accL[mi][o], a2, p0, p1);   // d2*e1
                }
            }
        }
    }

    // epilogue: combine digit classes, scale, tanh
    const float INVQ = 1.0f / (QSA * QSB);
    const int rbase = bm + wm + (lane >> 2);
    const int cbase = bn + wn + (lane & 3) * 2;
    #pragma unroll
    for (int mi = 0; mi < 4; ++mi) {
        #pragma unroll
        for (int o = 0; o < 4; ++o) {
            const long long r0 = rbase + mi * 16;
            const int col = cbase + o * 8;
            float v[4];
            #pragma unroll
            for (int q = 0; q < 4; ++q)
                v[q] = tanhf(((float)accH[mi][o][q] * 16384.0f +
                              (float)accL[mi][o][q] * 128.0f) * INVQ);
            *(float2*)(Cf + r0 * ldc + col)       = make_float2(v[0], v[1]);
            *(float2*)(Cf + (r0 + 8) * ldc + col) = make_float2(v[2], v[3]);
        }
    }
}

// --------------------------- auxiliary kernels -----------------------------
__global__ void __launch_bounds__(256)
split_k(const float4* __restrict__ x, uint2* __restrict__ h,
        uint2* __restrict__ l, int n4)
{
    const int i = blockIdx.x * 256 + threadIdx.x;
    if (i >= n4) return;
    const float4 v = x[i];
    hf h0 = __float2half_rn(v.x), h1 = __float2half_rn(v.y);
    hf h2 = __float2half_rn(v.z), h3 = __float2half_rn(v.w);
    hf l0 = __float2half_rn(v.x - __half2float(h0));
    hf l1 = __float2half_rn(v.y - __half2float(h1));
    hf l2 = __float2half_rn(v.z - __half2float(h2));
    hf l3 = __float2half_rn(v.w - __half2float(h3));
    h[i] = make_uint2(packh(h0, h1), packh(h2, h3));
    l[i] = make_uint2(packh(l0, l1), packh(l2, l3));
}

// 2-digit s8 quantization
__global__ void __launch_bounds__(256)
quant_k(const float4* __restrict__ x, char4* __restrict__ q1,
        char4* __restrict__ q2, int n4, float scale)
{
    const int i = blockIdx.x * 256 + threadIdx.x;
    if (i >= n4) return;
    const float4 v = x[i];
    int a1, a2, b1, b2, c1, c2, d1, d2;
    quant2(v.x, scale, a1, a2); quant2(v.y, scale, b1, b2);
    quant2(v.z, scale, c1, c2); quant2(v.w, scale, d1, d2);
    char4 p;
    p.x = (char)a1; p.y = (char)b1; p.z = (char)c1; p.w = (char)d1; q1[i] = p;
    p.x = (char)a2; p.y = (char)b2; p.z = (char)c2; p.w = (char)d2; q2[i] = p;
}

// encT[b][e][s] = enc[b][s][e], split hi/lo fp16
__global__ void __launch_bounds__(256)
tsplit_k(const float* __restrict__ x, hf* __restrict__ th, hf* __restrict__ tl)
{
    __shared__ float t[32][33];
    const long long z = blockIdx.z;
    const float* xp = x + z * (long long)SDIM * EDIM;
    hf* hp = th + z * (long long)EDIM * SDIM;
    hf* lp = tl + z * (long long)EDIM * SDIM;
    const int e0 = blockIdx.x * 32, s0 = blockIdx.y * 32;
    const int tx = threadIdx.x & 31, ty = threadIdx.x >> 5;
    #pragma unroll
    for (int j = 0; j < 4; ++j)
        t[ty + 8 * j][tx] = xp[(long long)(s0 + ty + 8 * j) * EDIM + e0 + tx];
    __syncthreads();
    #pragma unroll
    for (int j = 0; j < 4; ++j) {
        const float v = t[tx][ty + 8 * j];
        const hf h = __float2half_rn(v);
        const long long o = (long long)(e0 + ty + 8 * j) * SDIM + s0 + tx;
        hp[o] = h;
        lp[o] = __float2half_rn(v - __half2float(h));
    }
}

// row softmax (S=1024): fp32 weights out + fp16 hi/lo split
__global__ void __launch_bounds__(256)
softmax_sp(const float* __restrict__ E, float* __restrict__ W,
           hf* __restrict__ Wh, hf* __restrict__ Wl)
{
    __shared__ float red[8];
    const long long row = blockIdx.x;
    const float4* e = (const float4*)(E + (row << 10));
    float4* w = (float4*)(W + (row << 10));
    const int t = threadIdx.x;

    float4 v = e[t];
    float m = fmaxf(fmaxf(v.x, v.y), fmaxf(v.z, v.w));
    #pragma unroll
    for (int o = 16; o; o >>= 1) m = fmaxf(m, __shfl_xor_sync(0xffffffffu, m, o));
    if ((t & 31) == 0) red[t >> 5] = m;
    __syncthreads();
    m = red[0];
    #pragma unroll
    for (int i = 1; i < 8; i++) m = fmaxf(m, red[i]);
    __syncthreads();

    float e0 = expf(v.x - m), e1 = expf(v.y - m);
    float e2 = expf(v.z - m), e3 = expf(v.w - m);
    float s = e0 + e1 + e2 + e3;
    #pragma unroll
    for (int o = 16; o; o >>= 1) s += __shfl_xor_sync(0xffffffffu, s, o);
    if ((t & 31) == 0) red[t >> 5] = s;
    __syncthreads();
    s = red[0] + red[1] + red[2] + red[3] + red[4] + red[5] + red[6] + red[7];

    const float inv = 1.0f / s;
    const float w0 = e0 * inv, w1 = e1 * inv, w2 = e2 * inv, w3 = e3 * inv;
    w[t] = make_float4(w0, w1, w2, w3);

    hf h0 = __float2half_rn(w0), h1 = __float2half_rn(w1);
    hf h2 = __float2half_rn(w2), h3 = __float2half_rn(w3);
    hf l0 = __float2half_rn(w0 - __half2float(h0));
    hf l1 = __float2half_rn(w1 - __half2float(h1));
    hf l2 = __float2half_rn(w2 - __half2float(h2));
    hf l3 = __float2half_rn(w3 - __half2float(h3));
    ((uint2*)(Wh + (row << 10)))[t] = make_uint2(packh(h0, h1), packh(h2, h3));
    ((uint2*)(Wl + (row << 10)))[t] = make_uint2(packh(l0, l1), packh(l2, l3));
}

// -------------------------------- launcher ---------------------------------
extern "C" void kernel_launch(void* const* d_in, const int* in_sizes, int n_in,
                              void* d_out, int out_size)
{
    const float* hidden = (const float*)d_in[0];
    const float* enc    = (const float*)d_in[1];
    const float* Wa     = (const float*)d_in[2];
    const float* ba     = (const float*)d_in[3];
    const float* Wo     = (const float*)d_in[4];

    float* out = (float*)d_out;
    const long long SZ = (long long)NBT;
    float* htilde = out;
    float* wts    = out + SZ;
    float* enrg   = out + 2 * SZ;

    hf *enc_h, *enc_l, *encT_h, *encT_l, *hid_h, *hid_l, *proj_h, *proj_l;
    hf *wts_h, *wts_l, *wa_h, *wa_l;
    char *ctx_q1, *ctx_q2, *hid_q1, *hid_q2, *wo_q1, *wo_q2;
    cudaGetSymbolAddress((void**)&enc_h,  g_enc_h);  cudaGetSymbolAddress((void**)&enc_l,  g_enc_l);
    cudaGetSymbolAddress((void**)&encT_h, g_encT_h); cudaGetSymbolAddress((void**)&encT_l, g_encT_l);
    cudaGetSymbolAddress((void**)&hid_h,  g_hid_h);  cudaGetSymbolAddress((void**)&hid_l,  g_hid_l);
    cudaGetSymbolAddress((void**)&proj_h, g_proj_h); cudaGetSymbolAddress((void**)&proj_l, g_proj_l);
    cudaGetSymbolAddress((void**)&wts_h,  g_wts_h);  cudaGetSymbolAddress((void**)&wts_l,  g_wts_l);
    cudaGetSymbolAddress((void**)&wa_h,   g_wa_h);   cudaGetSymbolAddress((void**)&wa_l,   g_wa_l);
    cudaGetSymbolAddress((void**)&ctx_q1, g_ctx_q1); cudaGetSymbolAddress((void**)&ctx_q2, g_ctx_q2);
    cudaGetSymbolAddress((void**)&hid_q1, g_hid_q1); cudaGetSymbolAddress((void**)&hid_q2, g_hid_q2);
    cudaGetSymbolAddress((void**)&wo_q1,  g_wo_q1);  cudaGetSymbolAddress((void**)&wo_q2,  g_wo_q2);

    cudaFuncSetAttribute(mma_gemm<1, 3>, cudaFuncAttributeMaxDynamicSharedMemorySize, SMEM_BYTES);
    cudaFuncSetAttribute(mma_gemm<0, 3>, cudaFuncAttributeMaxDynamicSharedMemorySize, SMEM_BYTES);
    cudaFuncSetAttribute(mma_gemm<4, 2>, cudaFuncAttributeMaxDynamicSharedMemorySize, SMEM_BYTES);
    cudaFuncSetAttribute(imma_tanh, cudaFuncAttributeMaxDynamicSharedMemorySize, QSMEM_BYTES);

    // operand prep
    split_k<<<NBT / 4 / 256, 256>>>((const float4*)enc,    (uint2*)enc_h, (uint2*)enc_l, NBT / 4);
    split_k<<<NBT / 4 / 256, 256>>>((const float4*)hidden, (uint2*)hid_h, (uint2*)hid_l, NBT / 4);
    split_k<<<1024, 256>>>((const float4*)Wa, (uint2*)wa_h, (uint2*)wa_l, 1024 * 1024 / 4);
    tsplit_k<<<dim3(EDIM / 32, SDIM / 32, BATCH), 256>>>(enc, encT_h, encT_l);
    quant_k<<<NBT / 4 / 256, 256>>>((const float4*)hidden, (char4*)hid_q1, (char4*)hid_q2, NBT / 4, QSA);
    quant_k<<<2048, 256>>>((const float4*)Wo, (char4*)wo_q1, (char4*)wo_q2, 1024 * 2048 / 4, QSB);

    // Stage 1: proj = enc @ Wa^T + ba -> fp16 split  (3-term)
    mma_gemm<1, 3><<<dim3(DDIM / 128, (BATCH * SDIM) / 128, 1), 256, SMEM_BYTES>>>(
        enc_h, enc_l, wa_h, wa_l, ba,
        nullptr, proj_h, proj_l, EDIM / 64, EDIM, EDIM, DDIM, 0, 0, 0);

    // Stage 2: energies = hidden @ proj^T (batched, 3-term) -> fp32
    mma_gemm<0, 3><<<dim3(SDIM / 128, TDIM / 128, BATCH), 256, SMEM_BYTES>>>(
        hid_h, hid_l, proj_h, proj_l, nullptr,
        enrg, nullptr, nullptr, DDIM / 64, DDIM, DDIM, SDIM,
        (long long)TDIM * DDIM, (long long)SDIM * DDIM, (long long)TDIM * SDIM);

    // Stage 3: softmax -> fp32 weights + fp16 split
    softmax_sp<<<BATCH * TDIM, 256>>>(enrg, wts, wts_h, wts_l);

    // Stage 4: ctx = weights @ encT^T (batched, 2-term) -> s8 2-digit
    mma_gemm<4, 2><<<dim3(EDIM / 128, TDIM / 128, BATCH), 256, SMEM_BYTES>>>(
        wts_h, wts_l, encT_h, encT_l, nullptr,
        nullptr, (hf*)ctx_q1, (hf*)ctx_q2, SDIM / 64, SDIM, SDIM, EDIM,
        (long long)TDIM * SDIM, (long long)EDIM * SDIM, (long long)TDIM * EDIM);

    // Stage 5: h_tilde = tanh(ctx @ Wo[:, :E]^T + hidden @ Wo[:, E:]^T)  (int8)
    imma_tanh<<<dim3(DDIM / 128, (BATCH * TDIM) / 128, 1), 256, QSMEM_BYTES>>>(
        ctx_q1, ctx_q2, wo_q1, wo_q2,
        hid_q1, hid_q2, wo_q1 + EDIM, wo_q2 + EDIM,
        htilde, EDIM / 64, DDIM / 64, EDIM, EDIM + DDIM, DDIM, EDIM + DDIM, DDIM);
}

// round 10
// speedup vs baseline: 2.1742x; 2.1742x over previous
#include <cuda_runtime.h>
#include <cuda_fp16.h>
#include <cstdint>
#include <math.h>

// ---------------------------------------------------------------------------
// Luong 'general' attention, B=16, T=S=E=D=1024.
// Out: [h_tilde | attn_weights | attn_energies] fp32.
// GEMMs: mma.sync m16n8k16 fp16 hi/lo split, fp32 acc.
//   Stage 1 (proj):      3-term  (softmax precision chain)
//   Stage 2 (energies):  3-term
//   Stage 4 (ctx):       1-term  (sharp softmax -> error ~ fp16 ulp of ctx)
//   Stage 5 (h_tilde):   2-term  (B=W_out split)
// Block 128x128, 8 warps (2x4), warp tile 64x32, K-chunk 64, SW128 smem,
// 3-stage cp.async pipeline.
// ---------------------------------------------------------------------------

typedef __half hf;

#define BATCH 16
#define TDIM 1024
#define SDIM 1024
#define EDIM 1024
#define DDIM 1024
#define NBT (16 * 1024 * 1024)

__device__ __align__(256) hf g_enc_h[NBT],  g_enc_l[NBT];
__device__ __align__(256) hf g_encT_h[NBT];
__device__ __align__(256) hf g_hid_h[NBT],  g_hid_l[NBT];
__device__ __align__(256) hf g_proj_h[NBT], g_proj_l[NBT];
__device__ __align__(256) hf g_wts_h[NBT];
__device__ __align__(256) hf g_ctx_h[NBT];
__device__ __align__(256) hf g_wa_h[1024 * 1024], g_wa_l[1024 * 1024];
__device__ __align__(256) hf g_wo_h[1024 * 2048], g_wo_l[1024 * 2048];

// ------------------------------ PTX helpers --------------------------------
__device__ __forceinline__ uint32_t smem_u32(const void* p) {
    uint32_t a;
    asm("{ .reg .u64 t; cvta.to.shared.u64 t, %1; cvt.u32.u64 %0, t; }"
        : "=r"(a) : "l"(p));
    return a;
}
__device__ __forceinline__ uint32_t swz(uint32_t off) {  // SW128: 128B rows
    return off ^ ((off >> 3) & 0x70);
}

#define CP_ASYNC16(saddr, gptr) \
    asm volatile("cp.async.cg.shared.global [%0], [%1], 16;" \
                 :: "r"(saddr), "l"(gptr) : "memory")
#define CP_COMMIT() asm volatile("cp.async.commit_group;" ::: "memory")
#define CP_WAITN(n) asm volatile("cp.async.wait_group %0;" :: "n"(n) : "memory")

#define LDSM4(r0, r1, r2, r3, addr) \
    asm volatile("ldmatrix.sync.aligned.m8n8.x4.shared.b16 {%0,%1,%2,%3}, [%4];" \
                 : "=r"(r0), "=r"(r1), "=r"(r2), "=r"(r3) : "r"(addr))

#define MMA16816(d, a, b0, b1) \
    asm volatile("mma.sync.aligned.m16n8k16.row.col.f32.f16.f16.f32 " \
                 "{%0,%1,%2,%3}, {%4,%5,%6,%7}, {%8,%9}, {%0,%1,%2,%3};" \
                 : "+f"((d)[0]), "+f"((d)[1]), "+f"((d)[2]), "+f"((d)[3]) \
                 : "r"((a)[0]), "r"((a)[1]), "r"((a)[2]), "r"((a)[3]), \
                   "r"(b0), "r"(b1))

__device__ __forceinline__ uint32_t packh(hf a, hf b) {
    __half2 t; t.x = a; t.y = b;
    return *reinterpret_cast<uint32_t*>(&t);
}

// ------------------------------ GEMM kernel --------------------------------
// Buffer (64KB): [Ah 16K][Al 16K][Bh 16K][Bl 16K], 3-stage pipeline = 192KB.
#define BUF_BYTES 65536
#define SMEM_BYTES (3 * BUF_BYTES)

// NT terms: 3 = ah*bh + ah*bl + al*bh ; 2 = ah*bh + ah*bl ; 1 = ah*bh
template<int NT>
__device__ __forceinline__ void stage_loads(
    uint32_t sbuf, const hf* pah, const hf* pal, const hf* pbh, const hf* pbl,
    int bm, int bn, int ldA, int ldB, int k0, int tid)
{
    #pragma unroll
    for (int j = 0; j < 4; ++j) {
        const int idx = tid + j * 256;
        const int r = idx >> 3, g = idx & 7;
        const uint32_t so = swz((uint32_t)(r * 128 + g * 16));
        const size_t ao = (size_t)(bm + r) * ldA + k0 + g * 8;
        const size_t bo = (size_t)(bn + r) * ldB + k0 + g * 8;
        CP_ASYNC16(sbuf + so, pah + ao);
        if (NT == 3) CP_ASYNC16(sbuf + 16384 + so, pal + ao);
        CP_ASYNC16(sbuf + 32768 + so, pbh + bo);
        if (NT >= 2) CP_ASYNC16(sbuf + 49152 + so, pbl + bo);
    }
}

// EPI: 0 = f32 store, 1 = bias + fp16 split (h+l), 2 = fp16 h-only, 3 = tanh f32
template<int EPI, int NT>
__global__ void __launch_bounds__(256, 1)
mma_gemm(const hf* __restrict__ Ah, const hf* __restrict__ Al,
         const hf* __restrict__ Bh, const hf* __restrict__ Bl,
         const hf* __restrict__ A2h, const hf* __restrict__ A2l,
         const hf* __restrict__ B2h, const hf* __restrict__ B2l,
         const float* __restrict__ bias,
         float* __restrict__ Cf, hf* __restrict__ Ch, hf* __restrict__ Cl,
         int NC1, int NC2, int lda, int ldb, int lda2, int ldb2, int ldc,
         long long sA, long long sB, long long sC)
{
    extern __shared__ char smem[];
    const uint32_t sb = smem_u32(smem);
    const int tid  = threadIdx.x;
    const int wid  = tid >> 5;
    const int lane = tid & 31;
    const long long z = blockIdx.z;
    Ah += z * sA; Al += z * sA; Bh += z * sB; Bl += z * sB;
    if (EPI == 0 || EPI == 3) Cf += z * sC;
    else { Ch += z * sC; Cl += z * sC; }

    const int bm = blockIdx.y * 128;
    const int bn = blockIdx.x * 128;
    const int wm = (wid >> 2) * 64;
    const int wn = (wid & 3) * 32;

    float acc[4][4][4];
    #pragma unroll
    for (int i = 0; i < 4; i++)
        #pragma unroll
        for (int j = 0; j < 4; j++)
            #pragma unroll
            for (int q = 0; q < 4; q++) acc[i][j][q] = 0.0f;

    const int NC = NC1 + NC2;

    stage_loads<NT>(sb, Ah, Al, Bh, Bl, bm, bn, lda, ldb, 0, tid);
    CP_COMMIT();
    if (NC > 1) {
        if (1 < NC1) stage_loads<NT>(sb + BUF_BYTES, Ah, Al, Bh, Bl, bm, bn, lda, ldb, 64, tid);
        else         stage_loads<NT>(sb + BUF_BYTES, A2h, A2l, B2h, B2l, bm, bn, lda2, ldb2, 0, tid);
    }
    CP_COMMIT();

    for (int c = 0; c < NC; ++c) {
        CP_WAITN(1);
        __syncthreads();

        if (c + 2 < NC) {
            const int cn = c + 2;
            const uint32_t nb = sb + (uint32_t)(cn % 3) * BUF_BYTES;
            if (cn < NC1)
                stage_loads<NT>(nb, Ah, Al, Bh, Bl, bm, bn, lda, ldb, cn * 64, tid);
            else
                stage_loads<NT>(nb, A2h, A2l, B2h, B2l, bm, bn, lda2, ldb2, (cn - NC1) * 64, tid);
            CP_COMMIT();
        }

        const uint32_t ab = sb + (uint32_t)(c % 3) * BUF_BYTES;
        const uint32_t bb = ab + 32768;

        #pragma unroll
        for (int ks = 0; ks < 4; ++ks) {
            uint32_t ah[4][4], al[4][4], bh[2][4], bl[2][4];
            const int arow = wm + (lane & 15);
            const int akb  = ks * 32 + ((lane >> 4) << 4);
            #pragma unroll
            for (int mi = 0; mi < 4; ++mi) {
                const uint32_t ad = ab + swz((uint32_t)((arow + mi * 16) * 128 + akb));
                LDSM4(ah[mi][0], ah[mi][1], ah[mi][2], ah[mi][3], ad);
                if (NT == 3) LDSM4(al[mi][0], al[mi][1], al[mi][2], al[mi][3], ad + 16384);
            }
            const int brow = wn + (lane & 7) + ((lane >> 4) << 3);
            const int bkb  = ks * 32 + (((lane >> 3) & 1) << 4);
            #pragma unroll
            for (int nj = 0; nj < 2; ++nj) {
                const uint32_t bd = bb + swz((uint32_t)((brow + nj * 16) * 128 + bkb));
                LDSM4(bh[nj][0], bh[nj][1], bh[nj][2], bh[nj][3], bd);
                if (NT >= 2) LDSM4(bl[nj][0], bl[nj][1], bl[nj][2], bl[nj][3], bd + 16384);
            }
            #pragma unroll
            for (int mi = 0; mi < 4; ++mi)
                #pragma unroll
                for (int o = 0; o < 4; ++o) {
                    const uint32_t b0h = bh[o >> 1][(o & 1) * 2];
                    const uint32_t b1h = bh[o >> 1][(o & 1) * 2 + 1];
                    MMA16816(acc[mi][o], ah[mi], b0h, b1h);
                    if (NT >= 2) {
                        const uint32_t b0l = bl[o >> 1][(o & 1) * 2];
                        const uint32_t b1l = bl[o >> 1][(o & 1) * 2 + 1];
                        MMA16816(acc[mi][o], ah[mi], b0l, b1l);
                    }
                    if (NT == 3) MMA16816(acc[mi][o], al[mi], b0h, b1h);
                }
        }
    }

    // ------------------------------- epilogue ------------------------------
    const int rbase = bm + wm + (lane >> 2);
    const int cbase = bn + wn + (lane & 3) * 2;
    #pragma unroll
    for (int mi = 0; mi < 4; ++mi) {
        #pragma unroll
        for (int o = 0; o < 4; ++o) {
            const long long r0 = rbase + mi * 16;
            const int col = cbase + o * 8;
            float c0 = acc[mi][o][0], c1 = acc[mi][o][1];
            float c2 = acc[mi][o][2], c3 = acc[mi][o][3];
            if (EPI == 1) {
                const float bv0 = __ldg(bias + col), bv1 = __ldg(bias + col + 1);
                c0 += bv0; c1 += bv1; c2 += bv0; c3 += bv1;
            }
            if (EPI == 3) {
                c0 = tanhf(c0); c1 = tanhf(c1); c2 = tanhf(c2); c3 = tanhf(c3);
            }
            if (EPI == 0 || EPI == 3) {
                *(float2*)(Cf + r0 * ldc + col)       = make_float2(c0, c1);
                *(float2*)(Cf + (r0 + 8) * ldc + col) = make_float2(c2, c3);
            } else {
                hf h0 = __float2half_rn(c0), h1 = __float2half_rn(c1);
                hf h2 = __float2half_rn(c2), h3 = __float2half_rn(c3);
                *(uint32_t*)(Ch + r0 * ldc + col)       = packh(h0, h1);
                *(uint32_t*)(Ch + (r0 + 8) * ldc + col) = packh(h2, h3);
                if (EPI == 1) {
                    hf l0 = __float2half_rn(c0 - __half2float(h0));
                    hf l1 = __float2half_rn(c1 - __half2float(h1));
                    hf l2 = __float2half_rn(c2 - __half2float(h2));
                    hf l3 = __float2half_rn(c3 - __half2float(h3));
                    *(uint32_t*)(Cl + r0 * ldc + col)       = packh(l0, l1);
                    *(uint32_t*)(Cl + (r0 + 8) * ldc + col) = packh(l2, l3);
                }
            }
        }
    }
}

// --------------------------- auxiliary kernels -----------------------------
__global__ void __launch_bounds__(256)
split_k(const float4* __restrict__ x, uint2* __restrict__ h,
        uint2* __restrict__ l, int n4)
{
    const int i = blockIdx.x * 256 + threadIdx.x;
    if (i >= n4) return;
    const float4 v = x[i];
    hf h0 = __float2half_rn(v.x), h1 = __float2half_rn(v.y);
    hf h2 = __float2half_rn(v.z), h3 = __float2half_rn(v.w);
    hf l0 = __float2half_rn(v.x - __half2float(h0));
    hf l1 = __float2half_rn(v.y - __half2float(h1));
    hf l2 = __float2half_rn(v.z - __half2float(h2));
    hf l3 = __float2half_rn(v.w - __half2float(h3));
    h[i] = make_uint2(packh(h0, h1), packh(h2, h3));
    l[i] = make_uint2(packh(l0, l1), packh(l2, l3));
}

// encT[b][e][s] = enc[b][s][e], hi only
__global__ void __launch_bounds__(256)
tsplit_k(const float* __restrict__ x, hf* __restrict__ th)
{
    __shared__ float t[32][33];
    const long long z = blockIdx.z;
    const float* xp = x + z * (long long)SDIM * EDIM;
    hf* hp = th + z * (long long)EDIM * SDIM;
    const int e0 = blockIdx.x * 32, s0 = blockIdx.y * 32;
    const int tx = threadIdx.x & 31, ty = threadIdx.x >> 5;
    #pragma unroll
    for (int j = 0; j < 4; ++j)
        t[ty + 8 * j][tx] = xp[(long long)(s0 + ty + 8 * j) * EDIM + e0 + tx];
    __syncthreads();
    #pragma unroll
    for (int j = 0; j < 4; ++j) {
        const float v = t[tx][ty + 8 * j];
        const long long o = (long long)(e0 + ty + 8 * j) * SDIM + s0 + tx;
        hp[o] = __float2half_rn(v);
    }
}

// row softmax (S=1024): fp32 weights out + fp16 hi
__global__ void __launch_bounds__(256)
softmax_sp(const float* __restrict__ E, float* __restrict__ W,
           hf* __restrict__ Wh)
{
    __shared__ float red[8];
    const long long row = blockIdx.x;
    const float4* e = (const float4*)(E + (row << 10));
    float4* w = (float4*)(W + (row << 10));
    const int t = threadIdx.x;

    float4 v = e[t];
    float m = fmaxf(fmaxf(v.x, v.y), fmaxf(v.z, v.w));
    #pragma unroll
    for (int o = 16; o; o >>= 1) m = fmaxf(m, __shfl_xor_sync(0xffffffffu, m, o));
    if ((t & 31) == 0) red[t >> 5] = m;
    __syncthreads();
    m = red[0];
    #pragma unroll
    for (int i = 1; i < 8; i++) m = fmaxf(m, red[i]);
    __syncthreads();

    float e0 = expf(v.x - m), e1 = expf(v.y - m);
    float e2 = expf(v.z - m), e3 = expf(v.w - m);
    float s = e0 + e1 + e2 + e3;
    #pragma unroll
    for (int o = 16; o; o >>= 1) s += __shfl_xor_sync(0xffffffffu, s, o);
    if ((t & 31) == 0) red[t >> 5] = s;
    __syncthreads();
    s = red[0] + red[1] + red[2] + red[3] + red[4] + red[5] + red[6] + red[7];

    const float inv = 1.0f / s;
    const float w0 = e0 * inv, w1 = e1 * inv, w2 = e2 * inv, w3 = e3 * inv;
    w[t] = make_float4(w0, w1, w2, w3);
    ((uint2*)(Wh + (row << 10)))[t] = make_uint2(
        packh(__float2half_rn(w0), __float2half_rn(w1)),
        packh(__float2half_rn(w2), __float2half_rn(w3)));
}

// -------------------------------- launcher ---------------------------------
extern "C" void kernel_launch(void* const* d_in, const int* in_sizes, int n_in,
                              void* d_out, int out_size)
{
    const float* hidden = (const float*)d_in[0];
    const float* enc    = (const float*)d_in[1];
    const float* Wa     = (const float*)d_in[2];
    const float* ba     = (const float*)d_in[3];
    const float* Wo     = (const float*)d_in[4];

    float* out = (float*)d_out;
    const long long SZ = (long long)NBT;
    float* htilde = out;
    float* wts    = out + SZ;
    float* enrg   = out + 2 * SZ;

    hf *enc_h, *enc_l, *encT_h, *hid_h, *hid_l, *proj_h, *proj_l;
    hf *wts_h, *ctx_h, *wa_h, *wa_l, *wo_h, *wo_l;
    cudaGetSymbolAddress((void**)&enc_h,  g_enc_h);  cudaGetSymbolAddress((void**)&enc_l,  g_enc_l);
    cudaGetSymbolAddress((void**)&encT_h, g_encT_h);
    cudaGetSymbolAddress((void**)&hid_h,  g_hid_h);  cudaGetSymbolAddress((void**)&hid_l,  g_hid_l);
    cudaGetSymbolAddress((void**)&proj_h, g_proj_h); cudaGetSymbolAddress((void**)&proj_l, g_proj_l);
    cudaGetSymbolAddress((void**)&wts_h,  g_wts_h);
    cudaGetSymbolAddress((void**)&ctx_h,  g_ctx_h);
    cudaGetSymbolAddress((void**)&wa_h,   g_wa_h);   cudaGetSymbolAddress((void**)&wa_l,   g_wa_l);
    cudaGetSymbolAddress((void**)&wo_h,   g_wo_h);   cudaGetSymbolAddress((void**)&wo_l,   g_wo_l);

    cudaFuncSetAttribute(mma_gemm<1, 3>, cudaFuncAttributeMaxDynamicSharedMemorySize, SMEM_BYTES);
    cudaFuncSetAttribute(mma_gemm<0, 3>, cudaFuncAttributeMaxDynamicSharedMemorySize, SMEM_BYTES);
    cudaFuncSetAttribute(mma_gemm<2, 1>, cudaFuncAttributeMaxDynamicSharedMemorySize, SMEM_BYTES);
    cudaFuncSetAttribute(mma_gemm<3, 2>, cudaFuncAttributeMaxDynamicSharedMemorySize, SMEM_BYTES);

    // operand splits
    split_k<<<NBT / 4 / 256, 256>>>((const float4*)enc,    (uint2*)enc_h, (uint2*)enc_l, NBT / 4);
    split_k<<<NBT / 4 / 256, 256>>>((const float4*)hidden, (uint2*)hid_h, (uint2*)hid_l, NBT / 4);
    split_k<<<1024, 256>>>((const float4*)Wa, (uint2*)wa_h, (uint2*)wa_l, 1024 * 1024 / 4);
    split_k<<<2048, 256>>>((const float4*)Wo, (uint2*)wo_h, (uint2*)wo_l, 1024 * 2048 / 4);
    tsplit_k<<<dim3(EDIM / 32, SDIM / 32, BATCH), 256>>>(enc, encT_h);

    // Stage 1: proj = enc @ Wa^T + ba -> fp16 split (3-term)
    mma_gemm<1, 3><<<dim3(DDIM / 128, (BATCH * SDIM) / 128, 1), 256, SMEM_BYTES>>>(
        enc_h, enc_l, wa_h, wa_l, nullptr, nullptr, nullptr, nullptr, ba,
        nullptr, proj_h, proj_l, EDIM / 64, 0, EDIM, EDIM, 0, 0, DDIM, 0, 0, 0);

    // Stage 2: energies = hidden @ proj^T (batched, 3-term) -> fp32
    mma_gemm<0, 3><<<dim3(SDIM / 128, TDIM / 128, BATCH), 256, SMEM_BYTES>>>(
        hid_h, hid_l, proj_h, proj_l, nullptr, nullptr, nullptr, nullptr, nullptr,
        enrg, nullptr, nullptr, DDIM / 64, 0, DDIM, DDIM, 0, 0, SDIM,
        (long long)TDIM * DDIM, (long long)SDIM * DDIM, (long long)TDIM * SDIM);

    // Stage 3: softmax -> fp32 weights + fp16 hi
    softmax_sp<<<BATCH * TDIM, 256>>>(enrg, wts, wts_h);

    // Stage 4: ctx = wts_h @ encT_h^T (batched, 1-term) -> fp16 hi
    mma_gemm<2, 1><<<dim3(EDIM / 128, TDIM / 128, BATCH), 256, SMEM_BYTES>>>(
        wts_h, nullptr, encT_h, nullptr, nullptr, nullptr, nullptr, nullptr, nullptr,
        nullptr, ctx_h, nullptr, SDIM / 64, 0, SDIM, SDIM, 0, 0, EDIM,
        (long long)TDIM * SDIM, (long long)EDIM * SDIM, (long long)TDIM * EDIM);

    // Stage 5: h_tilde = tanh(ctx @ Wo[:, :E]^T + hidden @ Wo[:, E:]^T)  (2-term)
    mma_gemm<3, 2><<<dim3(DDIM / 128, (BATCH * TDIM) / 128, 1), 256, SMEM_BYTES>>>(
        ctx_h, nullptr, wo_h, wo_l, hid_h, nullptr, wo_h + EDIM, wo_l + EDIM, nullptr,
        htilde, nullptr, nullptr, EDIM / 64, DDIM / 64,
        EDIM, EDIM + DDIM, DDIM, EDIM + DDIM, DDIM, 0, 0, 0);
}

// round 11
// speedup vs baseline: 2.4994x; 1.1496x over previous
#include <cuda_runtime.h>
#include <cuda_fp16.h>
#include <cstdint>
#include <math.h>

// ---------------------------------------------------------------------------
// Luong 'general' attention, B=16, T=S=E=D=1024.
// Out: [h_tilde | attn_weights | attn_energies] fp32.
// GEMMs: mma.sync m16n8k16 fp16 hi/lo split, fp32 acc.
//   Stage 1 (proj):      3-term  (softmax precision chain)
//   Stage 2 (energies):  3-term
//   Stage 4 (ctx):       1-term
//   Stage 5 (h_tilde):   1-term  (err ~3.5e-4, 2.3x under gate)
// Block 128x128, 8 warps (2x4), warp tile 64x32, K-chunk 64, SW128 smem,
// 3-stage cp.async pipeline.
// ---------------------------------------------------------------------------

typedef __half hf;

#define BATCH 16
#define TDIM 1024
#define SDIM 1024
#define EDIM 1024
#define DDIM 1024
#define NBT (16 * 1024 * 1024)

__device__ __align__(256) hf g_enc_h[NBT],  g_enc_l[NBT];
__device__ __align__(256) hf g_encT_h[NBT];
__device__ __align__(256) hf g_hid_h[NBT],  g_hid_l[NBT];
__device__ __align__(256) hf g_proj_h[NBT], g_proj_l[NBT];
__device__ __align__(256) hf g_wts_h[NBT];
__device__ __align__(256) hf g_ctx_h[NBT];
__device__ __align__(256) hf g_wa_h[1024 * 1024], g_wa_l[1024 * 1024];
__device__ __align__(256) hf g_wo_h[1024 * 2048];

// ------------------------------ PTX helpers --------------------------------
__device__ __forceinline__ uint32_t smem_u32(const void* p) {
    uint32_t a;
    asm("{ .reg .u64 t; cvta.to.shared.u64 t, %1; cvt.u32.u64 %0, t; }"
        : "=r"(a) : "l"(p));
    return a;
}
__device__ __forceinline__ uint32_t swz(uint32_t off) {  // SW128: 128B rows
    return off ^ ((off >> 3) & 0x70);
}

#define CP_ASYNC16(saddr, gptr) \
    asm volatile("cp.async.cg.shared.global [%0], [%1], 16;" \
                 :: "r"(saddr), "l"(gptr) : "memory")
#define CP_COMMIT() asm volatile("cp.async.commit_group;" ::: "memory")
#define CP_WAITN(n) asm volatile("cp.async.wait_group %0;" :: "n"(n) : "memory")

#define LDSM4(r0, r1, r2, r3, addr) \
    asm volatile("ldmatrix.sync.aligned.m8n8.x4.shared.b16 {%0,%1,%2,%3}, [%4];" \
                 : "=r"(r0), "=r"(r1), "=r"(r2), "=r"(r3) : "r"(addr))

#define MMA16816(d, a, b0, b1) \
    asm volatile("mma.sync.aligned.m16n8k16.row.col.f32.f16.f16.f32 " \
                 "{%0,%1,%2,%3}, {%4,%5,%6,%7}, {%8,%9}, {%0,%1,%2,%3};" \
                 : "+f"((d)[0]), "+f"((d)[1]), "+f"((d)[2]), "+f"((d)[3]) \
                 : "r"((a)[0]), "r"((a)[1]), "r"((a)[2]), "r"((a)[3]), \
                   "r"(b0), "r"(b1))

__device__ __forceinline__ uint32_t packh(hf a, hf b) {
    __half2 t; t.x = a; t.y = b;
    return *reinterpret_cast<uint32_t*>(&t);
}

// ------------------------------ GEMM kernel --------------------------------
// Buffer (64KB): [Ah 16K][Al 16K][Bh 16K][Bl 16K], 3-stage pipeline = 192KB.
#define BUF_BYTES 65536
#define SMEM_BYTES (3 * BUF_BYTES)

// NT terms: 3 = ah*bh + ah*bl + al*bh ; 2 = ah*bh + ah*bl ; 1 = ah*bh
template<int NT>
__device__ __forceinline__ void stage_loads(
    uint32_t sbuf, const hf* pah, const hf* pal, const hf* pbh, const hf* pbl,
    int bm, int bn, int ldA, int ldB, int k0, int tid)
{
    #pragma unroll
    for (int j = 0; j < 4; ++j) {
        const int idx = tid + j * 256;
        const int r = idx >> 3, g = idx & 7;
        const uint32_t so = swz((uint32_t)(r * 128 + g * 16));
        const size_t ao = (size_t)(bm + r) * ldA + k0 + g * 8;
        const size_t bo = (size_t)(bn + r) * ldB + k0 + g * 8;
        CP_ASYNC16(sbuf + so, pah + ao);
        if (NT == 3) CP_ASYNC16(sbuf + 16384 + so, pal + ao);
        CP_ASYNC16(sbuf + 32768 + so, pbh + bo);
        if (NT >= 2) CP_ASYNC16(sbuf + 49152 + so, pbl + bo);
    }
}

// EPI: 0 = f32 store, 1 = bias + fp16 split (h+l), 2 = fp16 h-only, 3 = tanh f32
template<int EPI, int NT>
__global__ void __launch_bounds__(256, 1)
mma_gemm(const hf* __restrict__ Ah, const hf* __restrict__ Al,
         const hf* __restrict__ Bh, const hf* __restrict__ Bl,
         const hf* __restrict__ A2h, const hf* __restrict__ A2l,
         const hf* __restrict__ B2h, const hf* __restrict__ B2l,
         const float* __restrict__ bias,
         float* __restrict__ Cf, hf* __restrict__ Ch, hf* __restrict__ Cl,
         int NC1, int NC2, int lda, int ldb, int lda2, int ldb2, int ldc,
         long long sA, long long sB, long long sC)
{
    extern __shared__ char smem[];
    const uint32_t sb = smem_u32(smem);
    const int tid  = threadIdx.x;
    const int wid  = tid >> 5;
    const int lane = tid & 31;
    const long long z = blockIdx.z;
    Ah += z * sA; Al += z * sA; Bh += z * sB; Bl += z * sB;
    if (EPI == 0 || EPI == 3) Cf += z * sC;
    else { Ch += z * sC; Cl += z * sC; }

    const int bm = blockIdx.y * 128;
    const int bn = blockIdx.x * 128;
    const int wm = (wid >> 2) * 64;
    const int wn = (wid & 3) * 32;

    float acc[4][4][4];
    #pragma unroll
    for (int i = 0; i < 4; i++)
        #pragma unroll
        for (int j = 0; j < 4; j++)
            #pragma unroll
            for (int q = 0; q < 4; q++) acc[i][j][q] = 0.0f;

    const int NC = NC1 + NC2;

    stage_loads<NT>(sb, Ah, Al, Bh, Bl, bm, bn, lda, ldb, 0, tid);
    CP_COMMIT();
    if (NC > 1) {
        if (1 < NC1) stage_loads<NT>(sb + BUF_BYTES, Ah, Al, Bh, Bl, bm, bn, lda, ldb, 64, tid);
        else         stage_loads<NT>(sb + BUF_BYTES, A2h, A2l, B2h, B2l, bm, bn, lda2, ldb2, 0, tid);
    }
    CP_COMMIT();

    for (int c = 0; c < NC; ++c) {
        CP_WAITN(1);
        __syncthreads();

        if (c + 2 < NC) {
            const int cn = c + 2;
            const uint32_t nb = sb + (uint32_t)(cn % 3) * BUF_BYTES;
            if (cn < NC1)
                stage_loads<NT>(nb, Ah, Al, Bh, Bl, bm, bn, lda, ldb, cn * 64, tid);
            else
                stage_loads<NT>(nb, A2h, A2l, B2h, B2l, bm, bn, lda2, ldb2, (cn - NC1) * 64, tid);
            CP_COMMIT();
        }

        const uint32_t ab = sb + (uint32_t)(c % 3) * BUF_BYTES;
        const uint32_t bb = ab + 32768;

        #pragma unroll
        for (int ks = 0; ks < 4; ++ks) {
            uint32_t ah[4][4], al[4][4], bh[2][4], bl[2][4];
            const int arow = wm + (lane & 15);
            const int akb  = ks * 32 + ((lane >> 4) << 4);
            #pragma unroll
            for (int mi = 0; mi < 4; ++mi) {
                const uint32_t ad = ab + swz((uint32_t)((arow + mi * 16) * 128 + akb));
                LDSM4(ah[mi][0], ah[mi][1], ah[mi][2], ah[mi][3], ad);
                if (NT == 3) LDSM4(al[mi][0], al[mi][1], al[mi][2], al[mi][3], ad + 16384);
            }
            const int brow = wn + (lane & 7) + ((lane >> 4) << 3);
            const int bkb  = ks * 32 + (((lane >> 3) & 1) << 4);
            #pragma unroll
            for (int nj = 0; nj < 2; ++nj) {
                const uint32_t bd = bb + swz((uint32_t)((brow + nj * 16) * 128 + bkb));
                LDSM4(bh[nj][0], bh[nj][1], bh[nj][2], bh[nj][3], bd);
                if (NT >= 2) LDSM4(bl[nj][0], bl[nj][1], bl[nj][2], bl[nj][3], bd + 16384);
            }
            #pragma unroll
            for (int mi = 0; mi < 4; ++mi)
                #pragma unroll
                for (int o = 0; o < 4; ++o) {
                    const uint32_t b0h = bh[o >> 1][(o & 1) * 2];
                    const uint32_t b1h = bh[o >> 1][(o & 1) * 2 + 1];
                    MMA16816(acc[mi][o], ah[mi], b0h, b1h);
                    if (NT >= 2) {
                        const uint32_t b0l = bl[o >> 1][(o & 1) * 2];
                        const uint32_t b1l = bl[o >> 1][(o & 1) * 2 + 1];
                        MMA16816(acc[mi][o], ah[mi], b0l, b1l);
                    }
                    if (NT == 3) MMA16816(acc[mi][o], al[mi], b0h, b1h);
                }
        }
    }

    // ------------------------------- epilogue ------------------------------
    const int rbase = bm + wm + (lane >> 2);
    const int cbase = bn + wn + (lane & 3) * 2;
    #pragma unroll
    for (int mi = 0; mi < 4; ++mi) {
        #pragma unroll
        for (int o = 0; o < 4; ++o) {
            const long long r0 = rbase + mi * 16;
            const int col = cbase + o * 8;
            float c0 = acc[mi][o][0], c1 = acc[mi][o][1];
            float c2 = acc[mi][o][2], c3 = acc[mi][o][3];
            if (EPI == 1) {
                const float bv0 = __ldg(bias + col), bv1 = __ldg(bias + col + 1);
                c0 += bv0; c1 += bv1; c2 += bv0; c3 += bv1;
            }
            if (EPI == 3) {
                c0 = tanhf(c0); c1 = tanhf(c1); c2 = tanhf(c2); c3 = tanhf(c3);
            }
            if (EPI == 0 || EPI == 3) {
                *(float2*)(Cf + r0 * ldc + col)       = make_float2(c0, c1);
                *(float2*)(Cf + (r0 + 8) * ldc + col) = make_float2(c2, c3);
            } else {
                hf h0 = __float2half_rn(c0), h1 = __float2half_rn(c1);
                hf h2 = __float2half_rn(c2), h3 = __float2half_rn(c3);
                *(uint32_t*)(Ch + r0 * ldc + col)       = packh(h0, h1);
                *(uint32_t*)(Ch + (r0 + 8) * ldc + col) = packh(h2, h3);
                if (EPI == 1) {
                    hf l0 = __float2half_rn(c0 - __half2float(h0));
                    hf l1 = __float2half_rn(c1 - __half2float(h1));
                    hf l2 = __float2half_rn(c2 - __half2float(h2));
                    hf l3 = __float2half_rn(c3 - __half2float(h3));
                    *(uint32_t*)(Cl + r0 * ldc + col)       = packh(l0, l1);
                    *(uint32_t*)(Cl + (r0 + 8) * ldc + col) = packh(l2, l3);
                }
            }
        }
    }
}

// --------------------------- auxiliary kernels -----------------------------
__global__ void __launch_bounds__(256)
split_k(const float4* __restrict__ x, uint2* __restrict__ h,
        uint2* __restrict__ l, int n4)
{
    const int i = blockIdx.x * 256 + threadIdx.x;
    if (i >= n4) return;
    const float4 v = x[i];
    hf h0 = __float2half_rn(v.x), h1 = __float2half_rn(v.y);
    hf h2 = __float2half_rn(v.z), h3 = __float2half_rn(v.w);
    hf l0 = __float2half_rn(v.x - __half2float(h0));
    hf l1 = __float2half_rn(v.y - __half2float(h1));
    hf l2 = __float2half_rn(v.z - __half2float(h2));
    hf l3 = __float2half_rn(v.w - __half2float(h3));
    h[i] = make_uint2(packh(h0, h1), packh(h2, h3));
    l[i] = make_uint2(packh(l0, l1), packh(l2, l3));
}

// hi-only fp16 conversion
__global__ void __launch_bounds__(256)
cvt_k(const float4* __restrict__ x, uint2* __restrict__ h, int n4)
{
    const int i = blockIdx.x * 256 + threadIdx.x;
    if (i >= n4) return;
    const float4 v = x[i];
    h[i] = make_uint2(packh(__float2half_rn(v.x), __float2half_rn(v.y)),
                      packh(__float2half_rn(v.z), __float2half_rn(v.w)));
}

// encT[b][e][s] = enc[b][s][e], hi only
__global__ void __launch_bounds__(256)
tsplit_k(const float* __restrict__ x, hf* __restrict__ th)
{
    __shared__ float t[32][33];
    const long long z = blockIdx.z;
    const float* xp = x + z * (long long)SDIM * EDIM;
    hf* hp = th + z * (long long)EDIM * SDIM;
    const int e0 = blockIdx.x * 32, s0 = blockIdx.y * 32;
    const int tx = threadIdx.x & 31, ty = threadIdx.x >> 5;
    #pragma unroll
    for (int j = 0; j < 4; ++j)
        t[ty + 8 * j][tx] = xp[(long long)(s0 + ty + 8 * j) * EDIM + e0 + tx];
    __syncthreads();
    #pragma unroll
    for (int j = 0; j < 4; ++j) {
        const float v = t[tx][ty + 8 * j];
        const long long o = (long long)(e0 + ty + 8 * j) * SDIM + s0 + tx;
        hp[o] = __float2half_rn(v);
    }
}

// row softmax (S=1024): fp32 weights out + fp16 hi
__global__ void __launch_bounds__(256)
softmax_sp(const float* __restrict__ E, float* __restrict__ W,
           hf* __restrict__ Wh)
{
    __shared__ float red[8];
    const long long row = blockIdx.x;
    const float4* e = (const float4*)(E + (row << 10));
    float4* w = (float4*)(W + (row << 10));
    const int t = threadIdx.x;

    float4 v = e[t];
    float m = fmaxf(fmaxf(v.x, v.y), fmaxf(v.z, v.w));
    #pragma unroll
    for (int o = 16; o; o >>= 1) m = fmaxf(m, __shfl_xor_sync(0xffffffffu, m, o));
    if ((t & 31) == 0) red[t >> 5] = m;
    __syncthreads();
    m = red[0];
    #pragma unroll
    for (int i = 1; i < 8; i++) m = fmaxf(m, red[i]);
    __syncthreads();

    float e0 = expf(v.x - m), e1 = expf(v.y - m);
    float e2 = expf(v.z - m), e3 = expf(v.w - m);
    float s = e0 + e1 + e2 + e3;
    #pragma unroll
    for (int o = 16; o; o >>= 1) s += __shfl_xor_sync(0xffffffffu, s, o);
    if ((t & 31) == 0) red[t >> 5] = s;
    __syncthreads();
    s = red[0] + red[1] + red[2] + red[3] + red[4] + red[5] + red[6] + red[7];

    const float inv = 1.0f / s;
    const float w0 = e0 * inv, w1 = e1 * inv, w2 = e2 * inv, w3 = e3 * inv;
    w[t] = make_float4(w0, w1, w2, w3);
    ((uint2*)(Wh + (row << 10)))[t] = make_uint2(
        packh(__float2half_rn(w0), __float2half_rn(w1)),
        packh(__float2half_rn(w2), __float2half_rn(w3)));
}

// -------------------------------- launcher ---------------------------------
extern "C" void kernel_launch(void* const* d_in, const int* in_sizes, int n_in,
                              void* d_out, int out_size)
{
    const float* hidden = (const float*)d_in[0];
    const float* enc    = (const float*)d_in[1];
    const float* Wa     = (const float*)d_in[2];
    const float* ba     = (const float*)d_in[3];
    const float* Wo     = (const float*)d_in[4];

    float* out = (float*)d_out;
    const long long SZ = (long long)NBT;
    float* htilde = out;
    float* wts    = out + SZ;
    float* enrg   = out + 2 * SZ;

    hf *enc_h, *enc_l, *encT_h, *hid_h, *hid_l, *proj_h, *proj_l;
    hf *wts_h, *ctx_h, *wa_h, *wa_l, *wo_h;
    cudaGetSymbolAddress((void**)&enc_h,  g_enc_h);  cudaGetSymbolAddress((void**)&enc_l,  g_enc_l);
    cudaGetSymbolAddress((void**)&encT_h, g_encT_h);
    cudaGetSymbolAddress((void**)&hid_h,  g_hid_h);  cudaGetSymbolAddress((void**)&hid_l,  g_hid_l);
    cudaGetSymbolAddress((void**)&proj_h, g_proj_h); cudaGetSymbolAddress((void**)&proj_l, g_proj_l);
    cudaGetSymbolAddress((void**)&wts_h,  g_wts_h);
    cudaGetSymbolAddress((void**)&ctx_h,  g_ctx_h);
    cudaGetSymbolAddress((void**)&wa_h,   g_wa_h);   cudaGetSymbolAddress((void**)&wa_l,   g_wa_l);
    cudaGetSymbolAddress((void**)&wo_h,   g_wo_h);

    cudaFuncSetAttribute(mma_gemm<1, 3>, cudaFuncAttributeMaxDynamicSharedMemorySize, SMEM_BYTES);
    cudaFuncSetAttribute(mma_gemm<0, 3>, cudaFuncAttributeMaxDynamicSharedMemorySize, SMEM_BYTES);
    cudaFuncSetAttribute(mma_gemm<2, 1>, cudaFuncAttributeMaxDynamicSharedMemorySize, SMEM_BYTES);
    cudaFuncSetAttribute(mma_gemm<3, 1>, cudaFuncAttributeMaxDynamicSharedMemorySize, SMEM_BYTES);

    // operand prep
    split_k<<<NBT / 4 / 256, 256>>>((const float4*)enc,    (uint2*)enc_h, (uint2*)enc_l, NBT / 4);
    split_k<<<NBT / 4 / 256, 256>>>((const float4*)hidden, (uint2*)hid_h, (uint2*)hid_l, NBT / 4);
    split_k<<<1024, 256>>>((const float4*)Wa, (uint2*)wa_h, (uint2*)wa_l, 1024 * 1024 / 4);
    cvt_k<<<2048, 256>>>((const float4*)Wo, (uint2*)wo_h, 1024 * 2048 / 4);
    tsplit_k<<<dim3(EDIM / 32, SDIM / 32, BATCH), 256>>>(enc, encT_h);

    // Stage 1: proj = enc @ Wa^T + ba -> fp16 split (3-term)
    mma_gemm<1, 3><<<dim3(DDIM / 128, (BATCH * SDIM) / 128, 1), 256, SMEM_BYTES>>>(
        enc_h, enc_l, wa_h, wa_l, nullptr, nullptr, nullptr, nullptr, ba,
        nullptr, proj_h, proj_l, EDIM / 64, 0, EDIM, EDIM, 0, 0, DDIM, 0, 0, 0);

    // Stage 2: energies = hidden @ proj^T (batched, 3-term) -> fp32
    mma_gemm<0, 3><<<dim3(SDIM / 128, TDIM / 128, BATCH), 256, SMEM_BYTES>>>(
        hid_h, hid_l, proj_h, proj_l, nullptr, nullptr, nullptr, nullptr, nullptr,
        enrg, nullptr, nullptr, DDIM / 64, 0, DDIM, DDIM, 0, 0, SDIM,
        (long long)TDIM * DDIM, (long long)SDIM * DDIM, (long long)TDIM * SDIM);

    // Stage 3: softmax -> fp32 weights + fp16 hi
    softmax_sp<<<BATCH * TDIM, 256>>>(enrg, wts, wts_h);

    // Stage 4: ctx = wts_h @ encT_h^T (batched, 1-term) -> fp16 hi
    mma_gemm<2, 1><<<dim3(EDIM / 128, TDIM / 128, BATCH), 256, SMEM_BYTES>>>(
        wts_h, nullptr, encT_h, nullptr, nullptr, nullptr, nullptr, nullptr, nullptr,
        nullptr, ctx_h, nullptr, SDIM / 64, 0, SDIM, SDIM, 0, 0, EDIM,
        (long long)TDIM * SDIM, (long long)EDIM * SDIM, (long long)TDIM * EDIM);

    // Stage 5: h_tilde = tanh(ctx @ Wo[:, :E]^T + hidden @ Wo[:, E:]^T)  (1-term)
    mma_gemm<3, 1><<<dim3(DDIM / 128, (BATCH * TDIM) / 128, 1), 256, SMEM_BYTES>>>(
        ctx_h, nullptr, wo_h, nullptr, hid_h, nullptr, wo_h + EDIM, nullptr, nullptr,
        htilde, nullptr, nullptr, EDIM / 64, DDIM / 64,
        EDIM, EDIM + DDIM, DDIM, EDIM + DDIM, DDIM, 0, 0, 0);
}

// round 12
// speedup vs baseline: 2.5005x; 1.0005x over previous
#include <cuda_runtime.h>
#include <cuda_fp16.h>
#include <cstdint>
#include <math.h>

// ---------------------------------------------------------------------------
// Luong 'general' attention, B=16, T=S=E=D=1024.
// Out: [h_tilde | attn_weights | attn_energies] fp32.
// GEMMs: mma.sync m16n8k16 fp16 hi/lo split, fp32 acc.
//   Stage 1 (proj):      3-term   Stage 2 (energies): 3-term
//   Stage 4 (ctx):       1-term   Stage 5 (h_tilde):  1-term
// Term-major MMA ordering: same-accumulator reuse distance 16 issues
// (breaks acc dependency chains exposed by asm-volatile program order).
// Block 128x128, 8 warps (2x4), warp tile 64x32, K-chunk 64, SW128 smem,
// 3-stage cp.async pipeline.
// ---------------------------------------------------------------------------

typedef __half hf;

#define BATCH 16
#define TDIM 1024
#define SDIM 1024
#define EDIM 1024
#define DDIM 1024
#define NBT (16 * 1024 * 1024)

__device__ __align__(256) hf g_enc_h[NBT],  g_enc_l[NBT];
__device__ __align__(256) hf g_encT_h[NBT];
__device__ __align__(256) hf g_hid_h[NBT],  g_hid_l[NBT];
__device__ __align__(256) hf g_proj_h[NBT], g_proj_l[NBT];
__device__ __align__(256) hf g_wts_h[NBT];
__device__ __align__(256) hf g_ctx_h[NBT];
__device__ __align__(256) hf g_wa_h[1024 * 1024], g_wa_l[1024 * 1024];
__device__ __align__(256) hf g_wo_h[1024 * 2048];

// ------------------------------ PTX helpers --------------------------------
__device__ __forceinline__ uint32_t smem_u32(const void* p) {
    uint32_t a;
    asm("{ .reg .u64 t; cvta.to.shared.u64 t, %1; cvt.u32.u64 %0, t; }"
        : "=r"(a) : "l"(p));
    return a;
}
__device__ __forceinline__ uint32_t swz(uint32_t off) {  // SW128: 128B rows
    return off ^ ((off >> 3) & 0x70);
}

#define CP_ASYNC16(saddr, gptr) \
    asm volatile("cp.async.cg.shared.global [%0], [%1], 16;" \
                 :: "r"(saddr), "l"(gptr) : "memory")
#define CP_COMMIT() asm volatile("cp.async.commit_group;" ::: "memory")
#define CP_WAITN(n) asm volatile("cp.async.wait_group %0;" :: "n"(n) : "memory")

#define LDSM4(r0, r1, r2, r3, addr) \
    asm volatile("ldmatrix.sync.aligned.m8n8.x4.shared.b16 {%0,%1,%2,%3}, [%4];" \
                 : "=r"(r0), "=r"(r1), "=r"(r2), "=r"(r3) : "r"(addr))

#define MMA16816(d, a, b0, b1) \
    asm volatile("mma.sync.aligned.m16n8k16.row.col.f32.f16.f16.f32 " \
                 "{%0,%1,%2,%3}, {%4,%5,%6,%7}, {%8,%9}, {%0,%1,%2,%3};" \
                 : "+f"((d)[0]), "+f"((d)[1]), "+f"((d)[2]), "+f"((d)[3]) \
                 : "r"((a)[0]), "r"((a)[1]), "r"((a)[2]), "r"((a)[3]), \
                   "r"(b0), "r"(b1))

__device__ __forceinline__ uint32_t packh(hf a, hf b) {
    __half2 t; t.x = a; t.y = b;
    return *reinterpret_cast<uint32_t*>(&t);
}

// ------------------------------ GEMM kernel --------------------------------
// Buffer (64KB): [Ah 16K][Al 16K][Bh 16K][Bl 16K], 3-stage pipeline = 192KB.
#define BUF_BYTES 65536
#define SMEM_BYTES (3 * BUF_BYTES)

// NT terms: 3 = ah*bh + ah*bl + al*bh ; 2 = ah*bh + ah*bl ; 1 = ah*bh
template<int NT>
__device__ __forceinline__ void stage_loads(
    uint32_t sbuf, const hf* pah, const hf* pal, const hf* pbh, const hf* pbl,
    int bm, int bn, int ldA, int ldB, int k0, int tid)
{
    #pragma unroll
    for (int j = 0; j < 4; ++j) {
        const int idx = tid + j * 256;
        const int r = idx >> 3, g = idx & 7;
        const uint32_t so = swz((uint32_t)(r * 128 + g * 16));
        const size_t ao = (size_t)(bm + r) * ldA + k0 + g * 8;
        const size_t bo = (size_t)(bn + r) * ldB + k0 + g * 8;
        CP_ASYNC16(sbuf + so, pah + ao);
        if (NT == 3) CP_ASYNC16(sbuf + 16384 + so, pal + ao);
        CP_ASYNC16(sbuf + 32768 + so, pbh + bo);
        if (NT >= 2) CP_ASYNC16(sbuf + 49152 + so, pbl + bo);
    }
}

// EPI: 0 = f32 store, 1 = bias + fp16 split (h+l), 2 = fp16 h-only, 3 = tanh f32
template<int EPI, int NT>
__global__ void __launch_bounds__(256, 1)
mma_gemm(const hf* __restrict__ Ah, const hf* __restrict__ Al,
         const hf* __restrict__ Bh, const hf* __restrict__ Bl,
         const hf* __restrict__ A2h, const hf* __restrict__ A2l,
         const hf* __restrict__ B2h, const hf* __restrict__ B2l,
         const float* __restrict__ bias,
         float* __restrict__ Cf, hf* __restrict__ Ch, hf* __restrict__ Cl,
         int NC1, int NC2, int lda, int ldb, int lda2, int ldb2, int ldc,
         long long sA, long long sB, long long sC)
{
    extern __shared__ char smem[];
    const uint32_t sb = smem_u32(smem);
    const int tid  = threadIdx.x;
    const int wid  = tid >> 5;
    const int lane = tid & 31;
    const long long z = blockIdx.z;
    Ah += z * sA; Al += z * sA; Bh += z * sB; Bl += z * sB;
    if (EPI == 0 || EPI == 3) Cf += z * sC;
    else { Ch += z * sC; Cl += z * sC; }

    const int bm = blockIdx.y * 128;
    const int bn = blockIdx.x * 128;
    const int wm = (wid >> 2) * 64;
    const int wn = (wid & 3) * 32;

    float acc[4][4][4];
    #pragma unroll
    for (int i = 0; i < 4; i++)
        #pragma unroll
        for (int j = 0; j < 4; j++)
            #pragma unroll
            for (int q = 0; q < 4; q++) acc[i][j][q] = 0.0f;

    const int NC = NC1 + NC2;

    stage_loads<NT>(sb, Ah, Al, Bh, Bl, bm, bn, lda, ldb, 0, tid);
    CP_COMMIT();
    if (NC > 1) {
        if (1 < NC1) stage_loads<NT>(sb + BUF_BYTES, Ah, Al, Bh, Bl, bm, bn, lda, ldb, 64, tid);
        else         stage_loads<NT>(sb + BUF_BYTES, A2h, A2l, B2h, B2l, bm, bn, lda2, ldb2, 0, tid);
    }
    CP_COMMIT();

    for (int c = 0; c < NC; ++c) {
        CP_WAITN(1);
        __syncthreads();

        if (c + 2 < NC) {
            const int cn = c + 2;
            const uint32_t nb = sb + (uint32_t)(cn % 3) * BUF_BYTES;
            if (cn < NC1)
                stage_loads<NT>(nb, Ah, Al, Bh, Bl, bm, bn, lda, ldb, cn * 64, tid);
            else
                stage_loads<NT>(nb, A2h, A2l, B2h, B2l, bm, bn, lda2, ldb2, (cn - NC1) * 64, tid);
            CP_COMMIT();
        }

        const uint32_t ab = sb + (uint32_t)(c % 3) * BUF_BYTES;
        const uint32_t bb = ab + 32768;

        #pragma unroll
        for (int ks = 0; ks < 4; ++ks) {
            uint32_t ah[4][4], al[4][4], bh[2][4], bl[2][4];
            const int arow = wm + (lane & 15);
            const int akb  = ks * 32 + ((lane >> 4) << 4);
            #pragma unroll
            for (int mi = 0; mi < 4; ++mi) {
                const uint32_t ad = ab + swz((uint32_t)((arow + mi * 16) * 128 + akb));
                LDSM4(ah[mi][0], ah[mi][1], ah[mi][2], ah[mi][3], ad);
                if (NT == 3) LDSM4(al[mi][0], al[mi][1], al[mi][2], al[mi][3], ad + 16384);
            }
            const int brow = wn + (lane & 7) + ((lane >> 4) << 3);
            const int bkb  = ks * 32 + (((lane >> 3) & 1) << 4);
            #pragma unroll
            for (int nj = 0; nj < 2; ++nj) {
                const uint32_t bd = bb + swz((uint32_t)((brow + nj * 16) * 128 + bkb));
                LDSM4(bh[nj][0], bh[nj][1], bh[nj][2], bh[nj][3], bd);
                if (NT >= 2) LDSM4(bl[nj][0], bl[nj][1], bl[nj][2], bl[nj][3], bd + 16384);
            }
            // term-major: same-acc reuse distance = 16 MMA issues
            #pragma unroll
            for (int mi = 0; mi < 4; ++mi)
                #pragma unroll
                for (int o = 0; o < 4; ++o)
                    MMA16816(acc[mi][o], ah[mi],
                             bh[o >> 1][(o & 1) * 2], bh[o >> 1][(o & 1) * 2 + 1]);
            if (NT >= 2) {
                #pragma unroll
                for (int mi = 0; mi < 4; ++mi)
                    #pragma unroll
                    for (int o = 0; o < 4; ++o)
                        MMA16816(acc[mi][o], ah[mi],
                                 bl[o >> 1][(o & 1) * 2], bl[o >> 1][(o & 1) * 2 + 1]);
            }
            if (NT == 3) {
                #pragma unroll
                for (int mi = 0; mi < 4; ++mi)
                    #pragma unroll
                    for (int o = 0; o < 4; ++o)
                        MMA16816(acc[mi][o], al[mi],
                                 bh[o >> 1][(o & 1) * 2], bh[o >> 1][(o & 1) * 2 + 1]);
            }
        }
    }

    // ------------------------------- epilogue ------------------------------
    const int rbase = bm + wm + (lane >> 2);
    const int cbase = bn + wn + (lane & 3) * 2;
    #pragma unroll
    for (int mi = 0; mi < 4; ++mi) {
        #pragma unroll
        for (int o = 0; o < 4; ++o) {
            const long long r0 = rbase + mi * 16;
            const int col = cbase + o * 8;
            float c0 = acc[mi][o][0], c1 = acc[mi][o][1];
            float c2 = acc[mi][o][2], c3 = acc[mi][o][3];
            if (EPI == 1) {
                const float bv0 = __ldg(bias + col), bv1 = __ldg(bias + col + 1);
                c0 += bv0; c1 += bv1; c2 += bv0; c3 += bv1;
            }
            if (EPI == 3) {
                c0 = tanhf(c0); c1 = tanhf(c1); c2 = tanhf(c2); c3 = tanhf(c3);
            }
            if (EPI == 0 || EPI == 3) {
                *(float2*)(Cf + r0 * ldc + col)       = make_float2(c0, c1);
                *(float2*)(Cf + (r0 + 8) * ldc + col) = make_float2(c2, c3);
            } else {
                hf h0 = __float2half_rn(c0), h1 = __float2half_rn(c1);
                hf h2 = __float2half_rn(c2), h3 = __float2half_rn(c3);
                *(uint32_t*)(Ch + r0 * ldc + col)       = packh(h0, h1);
                *(uint32_t*)(Ch + (r0 + 8) * ldc + col) = packh(h2, h3);
                if (EPI == 1) {
                    hf l0 = __float2half_rn(c0 - __half2float(h0));
                    hf l1 = __float2half_rn(c1 - __half2float(h1));
                    hf l2 = __float2half_rn(c2 - __half2float(h2));
                    hf l3 = __float2half_rn(c3 - __half2float(h3));
                    *(uint32_t*)(Cl + r0 * ldc + col)       = packh(l0, l1);
                    *(uint32_t*)(Cl + (r0 + 8) * ldc + col) = packh(l2, l3);
                }
            }
        }
    }
}

// --------------------------- auxiliary kernels -----------------------------
__global__ void __launch_bounds__(256)
split_k(const float4* __restrict__ x, uint2* __restrict__ h,
        uint2* __restrict__ l, int n4)
{
    const int i = blockIdx.x * 256 + threadIdx.x;
    if (i >= n4) return;
    const float4 v = x[i];
    hf h0 = __float2half_rn(v.x), h1 = __float2half_rn(v.y);
    hf h2 = __float2half_rn(v.z), h3 = __float2half_rn(v.w);
    hf l0 = __float2half_rn(v.x - __half2float(h0));
    hf l1 = __float2half_rn(v.y - __half2float(h1));
    hf l2 = __float2half_rn(v.z - __half2float(h2));
    hf l3 = __float2half_rn(v.w - __half2float(h3));
    h[i] = make_uint2(packh(h0, h1), packh(h2, h3));
    l[i] = make_uint2(packh(l0, l1), packh(l2, l3));
}

// hi-only fp16 conversion
__global__ void __launch_bounds__(256)
cvt_k(const float4* __restrict__ x, uint2* __restrict__ h, int n4)
{
    const int i = blockIdx.x * 256 + threadIdx.x;
    if (i >= n4) return;
    const float4 v = x[i];
    h[i] = make_uint2(packh(__float2half_rn(v.x), __float2half_rn(v.y)),
                      packh(__float2half_rn(v.z), __float2half_rn(v.w)));
}

// encT[b][e][s] = enc[b][s][e], hi only
__global__ void __launch_bounds__(256)
tsplit_k(const float* __restrict__ x, hf* __restrict__ th)
{
    __shared__ float t[32][33];
    const long long z = blockIdx.z;
    const float* xp = x + z * (long long)SDIM * EDIM;
    hf* hp = th + z * (long long)EDIM * SDIM;
    const int e0 = blockIdx.x * 32, s0 = blockIdx.y * 32;
    const int tx = threadIdx.x & 31, ty = threadIdx.x >> 5;
    #pragma unroll
    for (int j = 0; j < 4; ++j)
        t[ty + 8 * j][tx] = xp[(long long)(s0 + ty + 8 * j) * EDIM + e0 + tx];
    __syncthreads();
    #pragma unroll
    for (int j = 0; j < 4; ++j) {
        const float v = t[tx][ty + 8 * j];
        const long long o = (long long)(e0 + ty + 8 * j) * SDIM + s0 + tx;
        hp[o] = __float2half_rn(v);
    }
}

// row softmax (S=1024): fp32 weights out + fp16 hi
__global__ void __launch_bounds__(256)
softmax_sp(const float* __restrict__ E, float* __restrict__ W,
           hf* __restrict__ Wh)
{
    __shared__ float red[8];
    const long long row = blockIdx.x;
    const float4* e = (const float4*)(E + (row << 10));
    float4* w = (float4*)(W + (row << 10));
    const int t = threadIdx.x;

    float4 v = e[t];
    float m = fmaxf(fmaxf(v.x, v.y), fmaxf(v.z, v.w));
    #pragma unroll
    for (int o = 16; o; o >>= 1) m = fmaxf(m, __shfl_xor_sync(0xffffffffu, m, o));
    if ((t & 31) == 0) red[t >> 5] = m;
    __syncthreads();
    m = red[0];
    #pragma unroll
    for (int i = 1; i < 8; i++) m = fmaxf(m, red[i]);
    __syncthreads();

    float e0 = expf(v.x - m), e1 = expf(v.y - m);
    float e2 = expf(v.z - m), e3 = expf(v.w - m);
    float s = e0 + e1 + e2 + e3;
    #pragma unroll
    for (int o = 16; o; o >>= 1) s += __shfl_xor_sync(0xffffffffu, s, o);
    if ((t & 31) == 0) red[t >> 5] = s;
    __syncthreads();
    s = red[0] + red[1] + red[2] + red[3] + red[4] + red[5] + red[6] + red[7];

    const float inv = 1.0f / s;
    const float w0 = e0 * inv, w1 = e1 * inv, w2 = e2 * inv, w3 = e3 * inv;
    w[t] = make_float4(w0, w1, w2, w3);
    ((uint2*)(Wh + (row << 10)))[t] = make_uint2(
        packh(__float2half_rn(w0), __float2half_rn(w1)),
        packh(__float2half_rn(w2), __float2half_rn(w3)));
}

// -------------------------------- launcher ---------------------------------
extern "C" void kernel_launch(void* const* d_in, const int* in_sizes, int n_in,
                              void* d_out, int out_size)
{
    const float* hidden = (const float*)d_in[0];
    const float* enc    = (const float*)d_in[1];
    const float* Wa     = (const float*)d_in[2];
    const float* ba     = (const float*)d_in[3];
    const float* Wo     = (const float*)d_in[4];

    float* out = (float*)d_out;
    const long long SZ = (long long)NBT;
    float* htilde = out;
    float* wts    = out + SZ;
    float* enrg   = out + 2 * SZ;

    hf *enc_h, *enc_l, *encT_h, *hid_h, *hid_l, *proj_h, *proj_l;
    hf *wts_h, *ctx_h, *wa_h, *wa_l, *wo_h;
    cudaGetSymbolAddress((void**)&enc_h,  g_enc_h);  cudaGetSymbolAddress((void**)&enc_l,  g_enc_l);
    cudaGetSymbolAddress((void**)&encT_h, g_encT_h);
    cudaGetSymbolAddress((void**)&hid_h,  g_hid_h);  cudaGetSymbolAddress((void**)&hid_l,  g_hid_l);
    cudaGetSymbolAddress((void**)&proj_h, g_proj_h); cudaGetSymbolAddress((void**)&proj_l, g_proj_l);
    cudaGetSymbolAddress((void**)&wts_h,  g_wts_h);
    cudaGetSymbolAddress((void**)&ctx_h,  g_ctx_h);
    cudaGetSymbolAddress((void**)&wa_h,   g_wa_h);   cudaGetSymbolAddress((void**)&wa_l,   g_wa_l);
    cudaGetSymbolAddress((void**)&wo_h,   g_wo_h);

    cudaFuncSetAttribute(mma_gemm<1, 3>, cudaFuncAttributeMaxDynamicSharedMemorySize, SMEM_BYTES);
    cudaFuncSetAttribute(mma_gemm<0, 3>, cudaFuncAttributeMaxDynamicSharedMemorySize, SMEM_BYTES);
    cudaFuncSetAttribute(mma_gemm<2, 1>, cudaFuncAttributeMaxDynamicSharedMemorySize, SMEM_BYTES);
    cudaFuncSetAttribute(mma_gemm<3, 1>, cudaFuncAttributeMaxDynamicSharedMemorySize, SMEM_BYTES);

    // operand prep
    split_k<<<NBT / 4 / 256, 256>>>((const float4*)enc,    (uint2*)enc_h, (uint2*)enc_l, NBT / 4);
    split_k<<<NBT / 4 / 256, 256>>>((const float4*)hidden, (uint2*)hid_h, (uint2*)hid_l, NBT / 4);
    split_k<<<1024, 256>>>((const float4*)Wa, (uint2*)wa_h, (uint2*)wa_l, 1024 * 1024 / 4);
    cvt_k<<<2048, 256>>>((const float4*)Wo, (uint2*)wo_h, 1024 * 2048 / 4);
    tsplit_k<<<dim3(EDIM / 32, SDIM / 32, BATCH), 256>>>(enc, encT_h);

    // Stage 1: proj = enc @ Wa^T + ba -> fp16 split (3-term)
    mma_gemm<1, 3><<<dim3(DDIM / 128, (BATCH * SDIM) / 128, 1), 256, SMEM_BYTES>>>(
        enc_h, enc_l, wa_h, wa_l, nullptr, nullptr, nullptr, nullptr, ba,
        nullptr, proj_h, proj_l, EDIM / 64, 0, EDIM, EDIM, 0, 0, DDIM, 0, 0, 0);

    // Stage 2: energies = hidden @ proj^T (batched, 3-term) -> fp32
    mma_gemm<0, 3><<<dim3(SDIM / 128, TDIM / 128, BATCH), 256, SMEM_BYTES>>>(
        hid_h, hid_l, proj_h, proj_l, nullptr, nullptr, nullptr, nullptr, nullptr,
        enrg, nullptr, nullptr, DDIM / 64, 0, DDIM, DDIM, 0, 0, SDIM,
        (long long)TDIM * DDIM, (long long)SDIM * DDIM, (long long)TDIM * SDIM);

    // Stage 3: softmax -> fp32 weights + fp16 hi
    softmax_sp<<<BATCH * TDIM, 256>>>(enrg, wts, wts_h);

    // Stage 4: ctx = wts_h @ encT_h^T (batched, 1-term) -> fp16 hi
    mma_gemm<2, 1><<<dim3(EDIM / 128, TDIM / 128, BATCH), 256, SMEM_BYTES>>>(
        wts_h, nullptr, encT_h, nullptr, nullptr, nullptr, nullptr, nullptr, nullptr,
        nullptr, ctx_h, nullptr, SDIM / 64, 0, SDIM, SDIM, 0, 0, EDIM,
        (long long)TDIM * SDIM, (long long)EDIM * SDIM, (long long)TDIM * EDIM);

    // Stage 5: h_tilde = tanh(ctx @ Wo[:, :E]^T + hidden @ Wo[:, E:]^T)  (1-term)
    mma_gemm<3, 1><<<dim3(DDIM / 128, (BATCH * TDIM) / 128, 1), 256, SMEM_BYTES>>>(
        ctx_h, nullptr, wo_h, nullptr, hid_h, nullptr, wo_h + EDIM, nullptr, nullptr,
        htilde, nullptr, nullptr, EDIM / 64, DDIM / 64,
        EDIM, EDIM + DDIM, DDIM, EDIM + DDIM, DDIM, 0, 0, 0);
}